// round 6
// baseline (speedup 1.0000x reference)
#include <cuda_runtime.h>
#include <math.h>

// Problem constants (fixed shapes)
#define B_    16
#define H_    16
#define BH    256          // B*H
#define L_    4
#define D_    2048
#define HD_   128
#define KV_   4096
#define KVT   4100         // KV + L
#define M_    64           // B*L rows
#define SPLITK 4

// Output layout (concatenated): out[131072], keys[256*4100*128], values[...]
#define OUT_ELEMS   (M_*D_)                 // 131072
#define KEYS_ELEMS  (BH*KVT*HD_)            // 134348800

// Scratch
__device__ float g_qkv[3*M_*D_];            // raw q,k,v projections
__device__ float g_q[BH*L_*HD_];            // roped q, (b,h,l,hd)
__device__ float g_attnout[BH*L_*HD_];      // attention output (b,h,l,hd)
__device__ float g_rc[L_][64];
__device__ float g_rs[L_][64];

// ---------------------------------------------------------------------------
// init: zero split-K accumulators + out region, build rope table (fp64 trig)
// ---------------------------------------------------------------------------
__global__ void __launch_bounds__(256) init_kernel(float* __restrict__ out) {
    int t = blockIdx.x * blockDim.x + threadIdx.x;
    if (t < 3*M_*D_) g_qkv[t] = 0.f;
    if (t < OUT_ELEMS) out[t] = 0.f;
    if (t < 256) {
        int l = t >> 6, i = t & 63;
        double inv = pow(10000.0, -(double)(2*i) / 128.0);
        float invf = (float)inv;                       // match jax f32 inv_freq
        float ang = (float)(KV_ + l) * invf;           // f32 angle like reference
        g_rc[l][i] = (float)cos((double)ang);
        g_rs[l][i] = (float)sin((double)ang);
    }
}

// ---------------------------------------------------------------------------
// Fused QKV projection: C[64 x 2048] += A[64 x 2048] * W[2048 x 2048]^T
// blockIdx.z selects q/k/v; blockIdx.y is the split-K slice (atomic combine).
// ---------------------------------------------------------------------------
__global__ void __launch_bounds__(256) gemm_qkv(const float* __restrict__ A,
                         const float* __restrict__ qw,
                         const float* __restrict__ kw,
                         const float* __restrict__ vw) {
    __shared__ float As[32][64];
    __shared__ float Bs[32][64];
    int mode = blockIdx.z;
    const float* __restrict__ W = (mode == 0) ? qw : ((mode == 1) ? kw : vw);
    float* __restrict__ C = g_qkv + mode * M_ * D_;

    int tid = threadIdx.x;
    int tx = tid & 15, ty = tid >> 4;
    int n0 = blockIdx.x * 64;
    int KS = D_ / gridDim.y;
    int kbase = blockIdx.y * KS;

    float acc[4][4] = {};

    for (int k0 = kbase; k0 < kbase + KS; k0 += 32) {
        #pragma unroll
        for (int rep = 0; rep < 2; rep++) {
            int fid = tid + rep * 256;
            int row = fid >> 3;
            int c4  = (fid & 7) * 4;
            int k   = k0 + c4;
            float4 av = *(const float4*)(A + row * D_ + k);
            float4 bv = *(const float4*)(W + (n0 + row) * D_ + k);
            As[c4+0][row] = av.x; As[c4+1][row] = av.y;
            As[c4+2][row] = av.z; As[c4+3][row] = av.w;
            Bs[c4+0][row] = bv.x; Bs[c4+1][row] = bv.y;
            Bs[c4+2][row] = bv.z; Bs[c4+3][row] = bv.w;
        }
        __syncthreads();
        #pragma unroll
        for (int kk = 0; kk < 32; kk++) {
            float a[4], b[4];
            #pragma unroll
            for (int i = 0; i < 4; i++) a[i] = As[kk][ty*4 + i];
            #pragma unroll
            for (int j = 0; j < 4; j++) b[j] = Bs[kk][tx*4 + j];
            #pragma unroll
            for (int i = 0; i < 4; i++)
                #pragma unroll
                for (int j = 0; j < 4; j++)
                    acc[i][j] += a[i] * b[j];
        }
        __syncthreads();
    }

    #pragma unroll
    for (int i = 0; i < 4; i++)
        #pragma unroll
        for (int j = 0; j < 4; j++)
            atomicAdd(&C[(ty*4 + i) * D_ + n0 + tx*4 + j], acc[i][j]);
}

// ---------------------------------------------------------------------------
// O projection: out[64 x 2048] += attnout(gathered) * OW^T, split-K atomic
// ---------------------------------------------------------------------------
__global__ void __launch_bounds__(256) gemm_o(const float* __restrict__ W,
                                              float* __restrict__ C) {
    __shared__ float As[32][64];
    __shared__ float Bs[32][64];
    const float* __restrict__ A = g_attnout;

    int tid = threadIdx.x;
    int tx = tid & 15, ty = tid >> 4;
    int n0 = blockIdx.x * 64;
    int KS = D_ / gridDim.y;
    int kbase = blockIdx.y * KS;

    float acc[4][4] = {};

    for (int k0 = kbase; k0 < kbase + KS; k0 += 32) {
        #pragma unroll
        for (int rep = 0; rep < 2; rep++) {
            int fid = tid + rep * 256;
            int row = fid >> 3;
            int c4  = (fid & 7) * 4;
            int k   = k0 + c4;
            // gather: A row m=(b,l), col k=(h,hd) from (b,h,l,hd) layout
            int b = row >> 2, l = row & 3, h = k >> 7, hd = k & 127;
            float4 av = *(const float4*)(A + (((b << 4) + h) * 4 + l) * HD_ + hd);
            float4 bv = *(const float4*)(W + (n0 + row) * D_ + k);
            As[c4+0][row] = av.x; As[c4+1][row] = av.y;
            As[c4+2][row] = av.z; As[c4+3][row] = av.w;
            Bs[c4+0][row] = bv.x; Bs[c4+1][row] = bv.y;
            Bs[c4+2][row] = bv.z; Bs[c4+3][row] = bv.w;
        }
        __syncthreads();
        #pragma unroll
        for (int kk = 0; kk < 32; kk++) {
            float a[4], b[4];
            #pragma unroll
            for (int i = 0; i < 4; i++) a[i] = As[kk][ty*4 + i];
            #pragma unroll
            for (int j = 0; j < 4; j++) b[j] = Bs[kk][tx*4 + j];
            #pragma unroll
            for (int i = 0; i < 4; i++)
                #pragma unroll
                for (int j = 0; j < 4; j++)
                    acc[i][j] += a[i] * b[j];
        }
        __syncthreads();
    }

    #pragma unroll
    for (int i = 0; i < 4; i++)
        #pragma unroll
        for (int j = 0; j < 4; j++)
            atomicAdd(&C[(ty*4 + i) * D_ + n0 + tx*4 + j], acc[i][j]);
}

// ---------------------------------------------------------------------------
// rope + scatter: q -> g_q (roped), k -> keys tail (roped), v -> values tail
// ---------------------------------------------------------------------------
__global__ void __launch_bounds__(256) rope_scatter(float* __restrict__ keys,
                                                    float* __restrict__ values) {
    int mat = blockIdx.y;                       // 0=q, 1=k, 2=v
    int p = blockIdx.x * 256 + threadIdx.x;     // pair id, 0..65535
    int m  = p >> 10;                            // row 0..63
    int n0 = (p & 1023) * 2;                     // even column
    int b = m >> 2, l = m & 3;
    int h = n0 >> 7, hd = n0 & 127;
    const float* src = g_qkv + mat * M_ * D_ + m * D_ + n0;
    float x1 = src[0], x2 = src[1];
    int bh = (b << 4) + h;
    if (mat == 2) {
        float* dst = values + (bh * KVT + KV_ + l) * HD_ + hd;
        dst[0] = x1; dst[1] = x2;
    } else {
        int i = hd >> 1;
        float c = g_rc[l][i], s = g_rs[l][i];
        float r1 = x1 * c - x2 * s;
        float r2 = x1 * s + x2 * c;
        if (mat == 0) {
            float* dst = g_q + (bh * 4 + l) * HD_ + hd;
            dst[0] = r1; dst[1] = r2;
        } else {
            float* dst = keys + (bh * KVT + KV_ + l) * HD_ + hd;
            dst[0] = r1; dst[1] = r2;
        }
    }
}

// ---------------------------------------------------------------------------
// Fused attention: one CTA per (b,h). Scores live entirely in smem.
// ---------------------------------------------------------------------------
__global__ void __launch_bounds__(256) attn_fused(
        const float* __restrict__ kc, const float* __restrict__ vc,
        const float* __restrict__ mask,
        float* __restrict__ keys, float* __restrict__ values) {
    extern __shared__ float sc[];               // 4*KVT floats = 65.6 KB
    __shared__ float redm[8], reds[8];
    int bh = blockIdx.x;
    int tid = threadIdx.x, w = tid >> 5, lane = tid & 31;

    const float* qb = g_q + bh * 4 * HD_ + lane * 4;
    float4 q0 = *(const float4*)(qb + 0 * HD_);
    float4 q1 = *(const float4*)(qb + 1 * HD_);
    float4 q2 = *(const float4*)(qb + 2 * HD_);
    float4 q3 = *(const float4*)(qb + 3 * HD_);

    const float scale = 0.08838834764831845f;   // 128^-0.5

    // ---- phase 1: K stream + scores ----
    #pragma unroll 4
    for (int r = w; r < KVT; r += 8) {
        float4 kv;
        int ko = (bh * KVT + r) * HD_ + lane * 4;
        if (r < KV_) {
            kv = *(const float4*)(kc + (bh * KV_ + r) * HD_ + lane * 4);
            *(float4*)(keys + ko) = kv;
        } else {
            kv = *(const float4*)(keys + ko);
        }
        float s0 = kv.x*q0.x + kv.y*q0.y + kv.z*q0.z + kv.w*q0.w;
        float s1 = kv.x*q1.x + kv.y*q1.y + kv.z*q1.z + kv.w*q1.w;
        float s2 = kv.x*q2.x + kv.y*q2.y + kv.z*q2.z + kv.w*q2.w;
        float s3 = kv.x*q3.x + kv.y*q3.y + kv.z*q3.z + kv.w*q3.w;
        #pragma unroll
        for (int off = 16; off; off >>= 1) {
            s0 += __shfl_xor_sync(0xFFFFFFFFu, s0, off);
            s1 += __shfl_xor_sync(0xFFFFFFFFu, s1, off);
            s2 += __shfl_xor_sync(0xFFFFFFFFu, s2, off);
            s3 += __shfl_xor_sync(0xFFFFFFFFu, s3, off);
        }
        if (lane == 0) {
            sc[0*KVT + r] = s0 * scale + mask[0*KVT + r];
            sc[1*KVT + r] = s1 * scale + mask[1*KVT + r];
            sc[2*KVT + r] = s2 * scale + mask[2*KVT + r];
            sc[3*KVT + r] = s3 * scale + mask[3*KVT + r];
        }
    }
    __syncthreads();

    // ---- phase 2: softmax, row = w>>1, 64 threads per row ----
    int row = w >> 1;
    int t64 = tid & 63;
    float* srow = sc + row * KVT;
    float mx = -3.0e38f;
    for (int i = t64; i < KVT; i += 64) mx = fmaxf(mx, srow[i]);
    #pragma unroll
    for (int off = 16; off; off >>= 1) mx = fmaxf(mx, __shfl_xor_sync(0xFFFFFFFFu, mx, off));
    if (lane == 0) redm[w] = mx;
    __syncthreads();
    float bm = fmaxf(redm[row*2], redm[row*2 + 1]);
    float sum = 0.f;
    for (int i = t64; i < KVT; i += 64) {
        float e = expf(srow[i] - bm);
        srow[i] = e;
        sum += e;
    }
    #pragma unroll
    for (int off = 16; off; off >>= 1) sum += __shfl_xor_sync(0xFFFFFFFFu, sum, off);
    if (lane == 0) reds[w] = sum;
    __syncthreads();
    float inv = 1.0f / (reds[row*2] + reds[row*2 + 1]);
    for (int i = t64; i < KVT; i += 64) srow[i] *= inv;
    __syncthreads();

    // ---- phase 3: V stream + probs @ V ----
    float a0[4] = {}, a1[4] = {}, a2[4] = {}, a3[4] = {};
    #pragma unroll 4
    for (int r = w; r < KVT; r += 8) {
        float4 v;
        int vo = (bh * KVT + r) * HD_ + lane * 4;
        if (r < KV_) {
            v = *(const float4*)(vc + (bh * KV_ + r) * HD_ + lane * 4);
            *(float4*)(values + vo) = v;
        } else {
            v = *(const float4*)(values + vo);
        }
        float p0 = sc[0*KVT + r], p1 = sc[1*KVT + r];
        float p2 = sc[2*KVT + r], p3 = sc[3*KVT + r];
        a0[0] += p0*v.x; a0[1] += p0*v.y; a0[2] += p0*v.z; a0[3] += p0*v.w;
        a1[0] += p1*v.x; a1[1] += p1*v.y; a1[2] += p1*v.z; a1[3] += p1*v.w;
        a2[0] += p2*v.x; a2[1] += p2*v.y; a2[2] += p2*v.z; a2[3] += p2*v.w;
        a3[0] += p3*v.x; a3[1] += p3*v.y; a3[2] += p3*v.z; a3[3] += p3*v.w;
    }
    __syncthreads();                    // probs dead; reuse sc for partials

    // ---- phase 4: cross-warp reduce -> g_attnout ----
    float* part = sc;                   // [8 warps][4 qi][128]
    *(float4*)&part[(w*4 + 0)*128 + lane*4] = make_float4(a0[0], a0[1], a0[2], a0[3]);
    *(float4*)&part[(w*4 + 1)*128 + lane*4] = make_float4(a1[0], a1[1], a1[2], a1[3]);
    *(float4*)&part[(w*4 + 2)*128 + lane*4] = make_float4(a2[0], a2[1], a2[2], a2[3]);
    *(float4*)&part[(w*4 + 3)*128 + lane*4] = make_float4(a3[0], a3[1], a3[2], a3[3]);
    __syncthreads();
    for (int o = tid; o < 512; o += 256) {
        int qi = o >> 7, c = o & 127;
        float s = 0.f;
        #pragma unroll
        for (int w2 = 0; w2 < 8; w2++) s += part[(w2*4 + qi)*128 + c];
        g_attnout[(bh*4 + qi)*HD_ + c] = s;
    }
}

// ---------------------------------------------------------------------------
extern "C" void kernel_launch(void* const* d_in, const int* in_sizes, int n_in,
                              void* d_out, int out_size) {
    const float* x    = (const float*)d_in[0];
    const float* mask = (const float*)d_in[1];
    const float* kc   = (const float*)d_in[2];
    const float* vc   = (const float*)d_in[3];
    const float* qw   = (const float*)d_in[4];
    const float* kw   = (const float*)d_in[5];
    const float* vw   = (const float*)d_in[6];
    const float* ow   = (const float*)d_in[7];

    float* out    = (float*)d_out;
    float* keys   = out + OUT_ELEMS;
    float* values = keys + KEYS_ELEMS;

    const int SMEM_ATTN = 4 * KVT * sizeof(float);   // 65600 bytes
    // Unconditional + idempotent: no static guards (harness determinism rule).
    cudaFuncSetAttribute(attn_fused, cudaFuncAttributeMaxDynamicSharedMemorySize,
                         SMEM_ATTN);

    init_kernel<<<1536, 256>>>(out);

    gemm_qkv<<<dim3(32, SPLITK, 3), 256>>>(x, qw, kw, vw);

    rope_scatter<<<dim3(256, 3), 256>>>(keys, values);

    attn_fused<<<BH, 256, SMEM_ATTN>>>(kc, vc, mask, keys, values);

    gemm_o<<<dim3(32, 4), 256>>>(ow, out);
}

// round 9
// speedup vs baseline: 1.4602x; 1.4602x over previous
#include <cuda_runtime.h>
#include <math.h>

// Problem constants (fixed shapes)
#define B_    16
#define H_    16
#define BH    256          // B*H
#define L_    4
#define D_    2048
#define HD_   128
#define KV_   4096
#define KVT   4100         // KV + L
#define M_    64           // B*L rows
#define CH    513          // kv chunk size
#define NCH   8            // 8*513 = 4104 >= 4100
#define SPLITK 4

// Output layout (concatenated): out[131072], keys[256*4100*128], values[...]
#define OUT_ELEMS   (M_*D_)                 // 131072
#define KEYS_ELEMS  (BH*KVT*HD_)            // 134348800

// Scratch
__device__ float g_qkv[3*M_*D_];            // raw q,k,v projections
__device__ float g_q[BH*L_*HD_];            // roped q, (b,h,l,hd)
__device__ float g_attnout[BH*L_*HD_];      // attention output accum (b,h,l,hd)
__device__ float g_scores[BH*L_*KVT];       // raw scores (pre-softmax)
__device__ float g_rowm[BH*L_];             // per-row max
__device__ float g_rowinv[BH*L_];           // per-row 1/sum(exp)
__device__ float g_rc[L_][64];
__device__ float g_rs[L_][64];

// ---------------------------------------------------------------------------
// init: zero accumulators + out region, build rope table (fp64 trig)
// ---------------------------------------------------------------------------
__global__ void __launch_bounds__(256) init_kernel(float* __restrict__ out) {
    int t = blockIdx.x * blockDim.x + threadIdx.x;
    if (t < 3*M_*D_) g_qkv[t] = 0.f;
    if (t < BH*L_*HD_) { g_attnout[t] = 0.f; out[t] = 0.f; }
    if (t < 256) {
        int l = t >> 6, i = t & 63;
        double inv = pow(10000.0, -(double)(2*i) / 128.0);
        float invf = (float)inv;                       // match jax f32 inv_freq
        float ang = (float)(KV_ + l) * invf;           // f32 angle like reference
        g_rc[l][i] = (float)cos((double)ang);
        g_rs[l][i] = (float)sin((double)ang);
    }
}

// ---------------------------------------------------------------------------
// Fused QKV projection: C[64 x 2048] += A[64 x 2048] * W[2048 x 2048]^T
// blockIdx.z selects q/k/v; blockIdx.y is the split-K slice (atomic combine).
// ---------------------------------------------------------------------------
__global__ void __launch_bounds__(256) gemm_qkv(const float* __restrict__ A,
                         const float* __restrict__ qw,
                         const float* __restrict__ kw,
                         const float* __restrict__ vw) {
    __shared__ float As[32][64];
    __shared__ float Bs[32][64];
    int mode = blockIdx.z;
    const float* __restrict__ W = (mode == 0) ? qw : ((mode == 1) ? kw : vw);
    float* __restrict__ C = g_qkv + mode * M_ * D_;

    int tid = threadIdx.x;
    int tx = tid & 15, ty = tid >> 4;
    int n0 = blockIdx.x * 64;
    int KS = D_ / gridDim.y;
    int kbase = blockIdx.y * KS;

    float acc[4][4] = {};

    for (int k0 = kbase; k0 < kbase + KS; k0 += 32) {
        #pragma unroll
        for (int rep = 0; rep < 2; rep++) {
            int fid = tid + rep * 256;
            int row = fid >> 3;
            int c4  = (fid & 7) * 4;
            int k   = k0 + c4;
            float4 av = *(const float4*)(A + row * D_ + k);
            float4 bv = *(const float4*)(W + (n0 + row) * D_ + k);
            As[c4+0][row] = av.x; As[c4+1][row] = av.y;
            As[c4+2][row] = av.z; As[c4+3][row] = av.w;
            Bs[c4+0][row] = bv.x; Bs[c4+1][row] = bv.y;
            Bs[c4+2][row] = bv.z; Bs[c4+3][row] = bv.w;
        }
        __syncthreads();
        #pragma unroll
        for (int kk = 0; kk < 32; kk++) {
            float a[4], b[4];
            #pragma unroll
            for (int i = 0; i < 4; i++) a[i] = As[kk][ty*4 + i];
            #pragma unroll
            for (int j = 0; j < 4; j++) b[j] = Bs[kk][tx*4 + j];
            #pragma unroll
            for (int i = 0; i < 4; i++)
                #pragma unroll
                for (int j = 0; j < 4; j++)
                    acc[i][j] += a[i] * b[j];
        }
        __syncthreads();
    }

    #pragma unroll
    for (int i = 0; i < 4; i++)
        #pragma unroll
        for (int j = 0; j < 4; j++)
            atomicAdd(&C[(ty*4 + i) * D_ + n0 + tx*4 + j], acc[i][j]);
}

// ---------------------------------------------------------------------------
// O projection: out[64 x 2048] += attnout(gathered) * OW^T, split-K atomic
// ---------------------------------------------------------------------------
__global__ void __launch_bounds__(256) gemm_o(const float* __restrict__ W,
                                              float* __restrict__ C) {
    __shared__ float As[32][64];
    __shared__ float Bs[32][64];
    const float* __restrict__ A = g_attnout;

    int tid = threadIdx.x;
    int tx = tid & 15, ty = tid >> 4;
    int n0 = blockIdx.x * 64;
    int KS = D_ / gridDim.y;
    int kbase = blockIdx.y * KS;

    float acc[4][4] = {};

    for (int k0 = kbase; k0 < kbase + KS; k0 += 32) {
        #pragma unroll
        for (int rep = 0; rep < 2; rep++) {
            int fid = tid + rep * 256;
            int row = fid >> 3;
            int c4  = (fid & 7) * 4;
            int k   = k0 + c4;
            // gather: A row m=(b,l), col k=(h,hd) from (b,h,l,hd) layout
            int b = row >> 2, l = row & 3, h = k >> 7, hd = k & 127;
            float4 av = *(const float4*)(A + (((b << 4) + h) * 4 + l) * HD_ + hd);
            float4 bv = *(const float4*)(W + (n0 + row) * D_ + k);
            As[c4+0][row] = av.x; As[c4+1][row] = av.y;
            As[c4+2][row] = av.z; As[c4+3][row] = av.w;
            Bs[c4+0][row] = bv.x; Bs[c4+1][row] = bv.y;
            Bs[c4+2][row] = bv.z; Bs[c4+3][row] = bv.w;
        }
        __syncthreads();
        #pragma unroll
        for (int kk = 0; kk < 32; kk++) {
            float a[4], b[4];
            #pragma unroll
            for (int i = 0; i < 4; i++) a[i] = As[kk][ty*4 + i];
            #pragma unroll
            for (int j = 0; j < 4; j++) b[j] = Bs[kk][tx*4 + j];
            #pragma unroll
            for (int i = 0; i < 4; i++)
                #pragma unroll
                for (int j = 0; j < 4; j++)
                    acc[i][j] += a[i] * b[j];
        }
        __syncthreads();
    }

    #pragma unroll
    for (int i = 0; i < 4; i++)
        #pragma unroll
        for (int j = 0; j < 4; j++)
            atomicAdd(&C[(ty*4 + i) * D_ + n0 + tx*4 + j], acc[i][j]);
}

// ---------------------------------------------------------------------------
// rope + scatter: q -> g_q (roped), k -> keys tail (roped), v -> values tail
// ---------------------------------------------------------------------------
__global__ void __launch_bounds__(256) rope_scatter(float* __restrict__ keys,
                                                    float* __restrict__ values) {
    int mat = blockIdx.y;                       // 0=q, 1=k, 2=v
    int p = blockIdx.x * 256 + threadIdx.x;     // pair id, 0..65535
    int m  = p >> 10;                            // row 0..63
    int n0 = (p & 1023) * 2;                     // even column
    int b = m >> 2, l = m & 3;
    int h = n0 >> 7, hd = n0 & 127;
    const float* src = g_qkv + mat * M_ * D_ + m * D_ + n0;
    float x1 = src[0], x2 = src[1];
    int bh = (b << 4) + h;
    if (mat == 2) {
        float* dst = values + (bh * KVT + KV_ + l) * HD_ + hd;
        dst[0] = x1; dst[1] = x2;
    } else {
        int i = hd >> 1;
        float c = g_rc[l][i], s = g_rs[l][i];
        float r1 = x1 * c - x2 * s;
        float r2 = x1 * s + x2 * c;
        if (mat == 0) {
            float* dst = g_q + (bh * 4 + l) * HD_ + hd;
            dst[0] = r1; dst[1] = r2;
        } else {
            float* dst = keys + (bh * KVT + KV_ + l) * HD_ + hd;
            dst[0] = r1; dst[1] = r2;
        }
    }
}

// ---------------------------------------------------------------------------
// Fused K-cache copy + scores: warp per kv row, float4 per lane.
// ---------------------------------------------------------------------------
__global__ void __launch_bounds__(256) kcopy_scores(
        const float* __restrict__ kc, const float* __restrict__ mask,
        float* __restrict__ keys) {
    int bh = blockIdx.x;
    int start = blockIdx.y * CH;
    int end = min(start + CH, KVT);
    int len = end - start;
    int tid = threadIdx.x, w = tid >> 5, lane = tid & 31;
    __shared__ float ssc[4][CH];

    const float* qb = g_q + bh * 4 * HD_ + lane * 4;
    float4 q0 = *(const float4*)(qb + 0 * HD_);
    float4 q1 = *(const float4*)(qb + 1 * HD_);
    float4 q2 = *(const float4*)(qb + 2 * HD_);
    float4 q3 = *(const float4*)(qb + 3 * HD_);

    for (int r = start + w; r < end; r += 8) {
        float4 kv;
        int ko = (bh * KVT + r) * HD_ + lane * 4;
        if (r < KV_) {
            kv = *(const float4*)(kc + (bh * KV_ + r) * HD_ + lane * 4);
            *(float4*)(keys + ko) = kv;
        } else {
            kv = *(const float4*)(keys + ko);
        }
        float s0 = kv.x*q0.x + kv.y*q0.y + kv.z*q0.z + kv.w*q0.w;
        float s1 = kv.x*q1.x + kv.y*q1.y + kv.z*q1.z + kv.w*q1.w;
        float s2 = kv.x*q2.x + kv.y*q2.y + kv.z*q2.z + kv.w*q2.w;
        float s3 = kv.x*q3.x + kv.y*q3.y + kv.z*q3.z + kv.w*q3.w;
        #pragma unroll
        for (int off = 16; off; off >>= 1) {
            s0 += __shfl_xor_sync(0xFFFFFFFFu, s0, off);
            s1 += __shfl_xor_sync(0xFFFFFFFFu, s1, off);
            s2 += __shfl_xor_sync(0xFFFFFFFFu, s2, off);
            s3 += __shfl_xor_sync(0xFFFFFFFFu, s3, off);
        }
        if (lane == 0) {
            ssc[0][r - start] = s0; ssc[1][r - start] = s1;
            ssc[2][r - start] = s2; ssc[3][r - start] = s3;
        }
    }
    __syncthreads();
    const float scale = 0.08838834764831845f;   // 128^-0.5
    #pragma unroll
    for (int qi = 0; qi < 4; qi++)
        for (int i = tid; i < len; i += 256)
            g_scores[(bh * 4 + qi) * KVT + start + i] =
                ssc[qi][i] * scale + mask[qi * KVT + start + i];
}

// ---------------------------------------------------------------------------
// Row stats: per-row max and 1/sum(exp) over 4100 elems (register-resident)
// ---------------------------------------------------------------------------
__global__ void __launch_bounds__(256) rowstat_k() {
    int row = blockIdx.x;                  // bh*4+qi, 0..1023
    const float* s = g_scores + row * KVT;
    int tid = threadIdx.x, lane = tid & 31, w = tid >> 5;
    __shared__ float red[8];

    float v[17];
    float mx = -3.0e38f;
    #pragma unroll
    for (int i = 0; i < 17; i++) {
        int idx = tid + i * 256;
        v[i] = (idx < KVT) ? s[idx] : -3.0e38f;
        mx = fmaxf(mx, v[i]);
    }
    #pragma unroll
    for (int off = 16; off; off >>= 1) mx = fmaxf(mx, __shfl_xor_sync(0xFFFFFFFFu, mx, off));
    if (lane == 0) red[w] = mx;
    __syncthreads();
    float bm = red[0];
    #pragma unroll
    for (int j = 1; j < 8; j++) bm = fmaxf(bm, red[j]);

    float sum = 0.f;
    #pragma unroll
    for (int i = 0; i < 17; i++) sum += expf(v[i] - bm);
    #pragma unroll
    for (int off = 16; off; off >>= 1) sum += __shfl_xor_sync(0xFFFFFFFFu, sum, off);
    __syncthreads();
    if (lane == 0) red[w] = sum;
    __syncthreads();
    if (tid == 0) {
        float tot = 0.f;
        #pragma unroll
        for (int j = 0; j < 8; j++) tot += red[j];
        g_rowm[row] = bm;
        g_rowinv[row] = 1.0f / tot;
    }
}

// ---------------------------------------------------------------------------
// Fused V-cache copy + attn @ V accumulation. Softmax normalization applied
// on the fly while staging probs into smem (raw scores -> exp((s-m))*inv).
// ---------------------------------------------------------------------------
__global__ void __launch_bounds__(256) vcopy_out(const float* __restrict__ vc,
                                                 float* __restrict__ values) {
    int bh = blockIdx.x;
    int start = blockIdx.y * CH;
    int end = min(start + CH, KVT);
    int len = end - start;
    int tid = threadIdx.x, w = tid >> 5, lane = tid & 31;
    __shared__ __align__(16) float sp[CH * 4];   // [row_local][qi]

    #pragma unroll
    for (int qi = 0; qi < 4; qi++) {
        float m   = g_rowm[bh * 4 + qi];
        float inv = g_rowinv[bh * 4 + qi];
        for (int i = tid; i < len; i += 256)
            sp[i * 4 + qi] = expf(g_scores[(bh * 4 + qi) * KVT + start + i] - m) * inv;
    }
    __syncthreads();

    float a0[4] = {}, a1[4] = {}, a2[4] = {}, a3[4] = {};
    for (int r = start + w; r < end; r += 8) {
        float4 v;
        int vo = (bh * KVT + r) * HD_ + lane * 4;
        if (r < KV_) {
            v = *(const float4*)(vc + (bh * KV_ + r) * HD_ + lane * 4);
            *(float4*)(values + vo) = v;
        } else {
            v = *(const float4*)(values + vo);
        }
        float4 p = *(const float4*)(sp + (r - start) * 4);
        a0[0] += p.x*v.x; a0[1] += p.x*v.y; a0[2] += p.x*v.z; a0[3] += p.x*v.w;
        a1[0] += p.y*v.x; a1[1] += p.y*v.y; a1[2] += p.y*v.z; a1[3] += p.y*v.w;
        a2[0] += p.z*v.x; a2[1] += p.z*v.y; a2[2] += p.z*v.z; a2[3] += p.z*v.w;
        a3[0] += p.w*v.x; a3[1] += p.w*v.y; a3[2] += p.w*v.z; a3[3] += p.w*v.w;
    }
    float* ao = g_attnout + bh * 4 * HD_ + lane * 4;
    #pragma unroll
    for (int e = 0; e < 4; e++) {
        atomicAdd(&ao[0 * HD_ + e], a0[e]);
        atomicAdd(&ao[1 * HD_ + e], a1[e]);
        atomicAdd(&ao[2 * HD_ + e], a2[e]);
        atomicAdd(&ao[3 * HD_ + e], a3[e]);
    }
}

// ---------------------------------------------------------------------------
extern "C" void kernel_launch(void* const* d_in, const int* in_sizes, int n_in,
                              void* d_out, int out_size) {
    const float* x    = (const float*)d_in[0];
    const float* mask = (const float*)d_in[1];
    const float* kc   = (const float*)d_in[2];
    const float* vc   = (const float*)d_in[3];
    const float* qw   = (const float*)d_in[4];
    const float* kw   = (const float*)d_in[5];
    const float* vw   = (const float*)d_in[6];
    const float* ow   = (const float*)d_in[7];

    float* out    = (float*)d_out;
    float* keys   = out + OUT_ELEMS;
    float* values = keys + KEYS_ELEMS;

    init_kernel<<<1536, 256>>>(out);

    gemm_qkv<<<dim3(32, SPLITK, 3), 256>>>(x, qw, kw, vw);

    rope_scatter<<<dim3(256, 3), 256>>>(keys, values);

    kcopy_scores<<<dim3(BH, NCH), 256>>>(kc, mask, keys);
    rowstat_k<<<BH * L_, 256>>>();
    vcopy_out<<<dim3(BH, NCH), 256>>>(vc, values);

    gemm_o<<<dim3(32, 4), 256>>>(ow, out);
}

// round 10
// speedup vs baseline: 1.6343x; 1.1192x over previous
#include <cuda_runtime.h>
#include <math.h>

// Problem constants (fixed shapes)
#define B_    16
#define H_    16
#define BH    256          // B*H
#define L_    4
#define D_    2048
#define HD_   128
#define KV_   4096
#define KVT   4100         // KV + L
#define M_    64           // B*L rows
#define CH2   512          // kv chunk size (8 chunks cover KV exactly)
#define SPLITK 4

// Output layout (concatenated): out[131072], keys[256*4100*128], values[...]
#define OUT_ELEMS   (M_*D_)                 // 131072
#define KEYS_ELEMS  (BH*KVT*HD_)            // 134348800

// Scratch
__device__ float g_qkv[3*M_*D_];            // raw q,k,v projections
__device__ float g_q[BH*L_*HD_];            // roped q, (b,h,l,hd)
__device__ float g_attnout[BH*L_*HD_];      // attention output accum (b,h,l,hd)
__device__ float g_scores[BH*L_*KVT];       // raw scores (pre-softmax)
__device__ float g_rowm[BH*L_];             // per-row max
__device__ float g_rowinv[BH*L_];           // per-row 1/sum(exp)
__device__ float g_rc[L_][64];
__device__ float g_rs[L_][64];

// ---------------------------------------------------------------------------
// init: zero accumulators + out region, build rope table (fp64 trig)
// ---------------------------------------------------------------------------
__global__ void __launch_bounds__(256) init_kernel(float* __restrict__ out) {
    int t = blockIdx.x * blockDim.x + threadIdx.x;
    if (t < 3*M_*D_) g_qkv[t] = 0.f;
    if (t < BH*L_*HD_) { g_attnout[t] = 0.f; out[t] = 0.f; }
    if (t < 256) {
        int l = t >> 6, i = t & 63;
        double inv = pow(10000.0, -(double)(2*i) / 128.0);
        float invf = (float)inv;                       // match jax f32 inv_freq
        float ang = (float)(KV_ + l) * invf;           // f32 angle like reference
        g_rc[l][i] = (float)cos((double)ang);
        g_rs[l][i] = (float)sin((double)ang);
    }
}

// ---------------------------------------------------------------------------
// Fused QKV projection: C[64 x 2048] += A[64 x 2048] * W[2048 x 2048]^T
// blockIdx.z selects q/k/v; blockIdx.y is the split-K slice (atomic combine).
// ---------------------------------------------------------------------------
__global__ void __launch_bounds__(256) gemm_qkv(const float* __restrict__ A,
                         const float* __restrict__ qw,
                         const float* __restrict__ kw,
                         const float* __restrict__ vw) {
    __shared__ float As[32][64];
    __shared__ float Bs[32][64];
    int mode = blockIdx.z;
    const float* __restrict__ W = (mode == 0) ? qw : ((mode == 1) ? kw : vw);
    float* __restrict__ C = g_qkv + mode * M_ * D_;

    int tid = threadIdx.x;
    int tx = tid & 15, ty = tid >> 4;
    int n0 = blockIdx.x * 64;
    int KS = D_ / gridDim.y;
    int kbase = blockIdx.y * KS;

    float acc[4][4] = {};

    for (int k0 = kbase; k0 < kbase + KS; k0 += 32) {
        #pragma unroll
        for (int rep = 0; rep < 2; rep++) {
            int fid = tid + rep * 256;
            int row = fid >> 3;
            int c4  = (fid & 7) * 4;
            int k   = k0 + c4;
            float4 av = *(const float4*)(A + row * D_ + k);
            float4 bv = *(const float4*)(W + (n0 + row) * D_ + k);
            As[c4+0][row] = av.x; As[c4+1][row] = av.y;
            As[c4+2][row] = av.z; As[c4+3][row] = av.w;
            Bs[c4+0][row] = bv.x; Bs[c4+1][row] = bv.y;
            Bs[c4+2][row] = bv.z; Bs[c4+3][row] = bv.w;
        }
        __syncthreads();
        #pragma unroll
        for (int kk = 0; kk < 32; kk++) {
            float a[4], b[4];
            #pragma unroll
            for (int i = 0; i < 4; i++) a[i] = As[kk][ty*4 + i];
            #pragma unroll
            for (int j = 0; j < 4; j++) b[j] = Bs[kk][tx*4 + j];
            #pragma unroll
            for (int i = 0; i < 4; i++)
                #pragma unroll
                for (int j = 0; j < 4; j++)
                    acc[i][j] += a[i] * b[j];
        }
        __syncthreads();
    }

    #pragma unroll
    for (int i = 0; i < 4; i++)
        #pragma unroll
        for (int j = 0; j < 4; j++)
            atomicAdd(&C[(ty*4 + i) * D_ + n0 + tx*4 + j], acc[i][j]);
}

// ---------------------------------------------------------------------------
// O projection: out[64 x 2048] += attnout(gathered) * OW^T, split-K atomic
// ---------------------------------------------------------------------------
__global__ void __launch_bounds__(256) gemm_o(const float* __restrict__ W,
                                              float* __restrict__ C) {
    __shared__ float As[32][64];
    __shared__ float Bs[32][64];
    const float* __restrict__ A = g_attnout;

    int tid = threadIdx.x;
    int tx = tid & 15, ty = tid >> 4;
    int n0 = blockIdx.x * 64;
    int KS = D_ / gridDim.y;
    int kbase = blockIdx.y * KS;

    float acc[4][4] = {};

    for (int k0 = kbase; k0 < kbase + KS; k0 += 32) {
        #pragma unroll
        for (int rep = 0; rep < 2; rep++) {
            int fid = tid + rep * 256;
            int row = fid >> 3;
            int c4  = (fid & 7) * 4;
            int k   = k0 + c4;
            // gather: A row m=(b,l), col k=(h,hd) from (b,h,l,hd) layout
            int b = row >> 2, l = row & 3, h = k >> 7, hd = k & 127;
            float4 av = *(const float4*)(A + (((b << 4) + h) * 4 + l) * HD_ + hd);
            float4 bv = *(const float4*)(W + (n0 + row) * D_ + k);
            As[c4+0][row] = av.x; As[c4+1][row] = av.y;
            As[c4+2][row] = av.z; As[c4+3][row] = av.w;
            Bs[c4+0][row] = bv.x; Bs[c4+1][row] = bv.y;
            Bs[c4+2][row] = bv.z; Bs[c4+3][row] = bv.w;
        }
        __syncthreads();
        #pragma unroll
        for (int kk = 0; kk < 32; kk++) {
            float a[4], b[4];
            #pragma unroll
            for (int i = 0; i < 4; i++) a[i] = As[kk][ty*4 + i];
            #pragma unroll
            for (int j = 0; j < 4; j++) b[j] = Bs[kk][tx*4 + j];
            #pragma unroll
            for (int i = 0; i < 4; i++)
                #pragma unroll
                for (int j = 0; j < 4; j++)
                    acc[i][j] += a[i] * b[j];
        }
        __syncthreads();
    }

    #pragma unroll
    for (int i = 0; i < 4; i++)
        #pragma unroll
        for (int j = 0; j < 4; j++)
            atomicAdd(&C[(ty*4 + i) * D_ + n0 + tx*4 + j], acc[i][j]);
}

// ---------------------------------------------------------------------------
// rope + scatter: q -> g_q (roped), k -> keys tail (roped), v -> values tail
// ---------------------------------------------------------------------------
__global__ void __launch_bounds__(256) rope_scatter(float* __restrict__ keys,
                                                    float* __restrict__ values) {
    int mat = blockIdx.y;                       // 0=q, 1=k, 2=v
    int p = blockIdx.x * 256 + threadIdx.x;     // pair id, 0..65535
    int m  = p >> 10;                            // row 0..63
    int n0 = (p & 1023) * 2;                     // even column
    int b = m >> 2, l = m & 3;
    int h = n0 >> 7, hd = n0 & 127;
    const float* src = g_qkv + mat * M_ * D_ + m * D_ + n0;
    float x1 = src[0], x2 = src[1];
    int bh = (b << 4) + h;
    if (mat == 2) {
        float* dst = values + (bh * KVT + KV_ + l) * HD_ + hd;
        dst[0] = x1; dst[1] = x2;
    } else {
        int i = hd >> 1;
        float c = g_rc[l][i], s = g_rs[l][i];
        float r1 = x1 * c - x2 * s;
        float r2 = x1 * s + x2 * c;
        if (mat == 0) {
            float* dst = g_q + (bh * 4 + l) * HD_ + hd;
            dst[0] = r1; dst[1] = r2;
        } else {
            float* dst = keys + (bh * KVT + KV_ + l) * HD_ + hd;
            dst[0] = r1; dst[1] = r2;
        }
    }
}

// ---------------------------------------------------------------------------
// helpers for the streaming kernels
// ---------------------------------------------------------------------------
__device__ __forceinline__ void dot4(float4 kv, float4 q0, float4 q1,
                                     float4 q2, float4 q3,
                                     float& s0, float& s1, float& s2, float& s3) {
    s0 = kv.x*q0.x + kv.y*q0.y + kv.z*q0.z + kv.w*q0.w;
    s1 = kv.x*q1.x + kv.y*q1.y + kv.z*q1.z + kv.w*q1.w;
    s2 = kv.x*q2.x + kv.y*q2.y + kv.z*q2.z + kv.w*q2.w;
    s3 = kv.x*q3.x + kv.y*q3.y + kv.z*q3.z + kv.w*q3.w;
}

__device__ __forceinline__ void red4(float& s0, float& s1, float& s2, float& s3) {
    #pragma unroll
    for (int off = 16; off; off >>= 1) {
        s0 += __shfl_xor_sync(0xFFFFFFFFu, s0, off);
        s1 += __shfl_xor_sync(0xFFFFFFFFu, s1, off);
        s2 += __shfl_xor_sync(0xFFFFFFFFu, s2, off);
        s3 += __shfl_xor_sync(0xFFFFFFFFu, s3, off);
    }
}

// ---------------------------------------------------------------------------
// Fused K-cache copy + scores: warp per kv row, 2 rows in flight per warp,
// branchless main loop over exactly 512 rows/chunk; tail rows in chunk 7.
// ---------------------------------------------------------------------------
__global__ void __launch_bounds__(256) kcopy_scores(
        const float* __restrict__ kc, const float* __restrict__ mask,
        float* __restrict__ keys) {
    int bh = blockIdx.x;
    int start = blockIdx.y * CH2;               // 0..3584, chunks cover [0,4096)
    bool last = (blockIdx.y == 7);
    int tid = threadIdx.x, w = tid >> 5, lane = tid & 31;
    __shared__ float ssc[4][CH2 + 4];

    const float* qb = g_q + bh * 4 * HD_ + lane * 4;
    float4 q0 = *(const float4*)(qb + 0 * HD_);
    float4 q1 = *(const float4*)(qb + 1 * HD_);
    float4 q2 = *(const float4*)(qb + 2 * HD_);
    float4 q3 = *(const float4*)(qb + 3 * HD_);

    const float* kin = kc   + (bh * KV_ + start) * HD_ + lane * 4;
    float*       kout = keys + (bh * KVT + start) * HD_ + lane * 4;

    for (int rr = w; rr < CH2; rr += 16) {
        // issue both loads before any dependent work (MLP=2 per warp)
        float4 ka = *(const float4*)(kin + rr * HD_);
        float4 kb = *(const float4*)(kin + (rr + 8) * HD_);
        *(float4*)(kout + rr * HD_)       = ka;
        *(float4*)(kout + (rr + 8) * HD_) = kb;
        float a0, a1, a2, a3, b0, b1, b2, b3;
        dot4(ka, q0, q1, q2, q3, a0, a1, a2, a3);
        dot4(kb, q0, q1, q2, q3, b0, b1, b2, b3);
        red4(a0, a1, a2, a3);
        red4(b0, b1, b2, b3);
        if (lane == 0) {
            ssc[0][rr] = a0; ssc[1][rr] = a1; ssc[2][rr] = a2; ssc[3][rr] = a3;
            ssc[0][rr+8] = b0; ssc[1][rr+8] = b1; ssc[2][rr+8] = b2; ssc[3][rr+8] = b3;
        }
    }

    if (last && w < 4) {                         // tail rows 4096..4099 (already in keys)
        int r = KV_ + w;
        float4 kv = *(const float4*)(keys + (bh * KVT + r) * HD_ + lane * 4);
        float t0, t1, t2, t3;
        dot4(kv, q0, q1, q2, q3, t0, t1, t2, t3);
        red4(t0, t1, t2, t3);
        if (lane == 0) {
            ssc[0][CH2 + w] = t0; ssc[1][CH2 + w] = t1;
            ssc[2][CH2 + w] = t2; ssc[3][CH2 + w] = t3;
        }
    }
    __syncthreads();

    const float scale = 0.08838834764831845f;   // 128^-0.5
    int len = last ? (CH2 + 4) : CH2;
    #pragma unroll
    for (int qi = 0; qi < 4; qi++)
        for (int i = tid; i < len; i += 256)
            g_scores[(bh * 4 + qi) * KVT + start + i] =
                ssc[qi][i] * scale + mask[qi * KVT + start + i];
}

// ---------------------------------------------------------------------------
// Row stats: per-row max and 1/sum(exp) over 4100 elems (register-resident)
// ---------------------------------------------------------------------------
__global__ void __launch_bounds__(256) rowstat_k() {
    int row = blockIdx.x;                  // bh*4+qi, 0..1023
    const float* s = g_scores + row * KVT;
    int tid = threadIdx.x, lane = tid & 31, w = tid >> 5;
    __shared__ float red[8];

    float v[17];
    float mx = -3.0e38f;
    #pragma unroll
    for (int i = 0; i < 17; i++) {
        int idx = tid + i * 256;
        v[i] = (idx < KVT) ? s[idx] : -3.0e38f;
        mx = fmaxf(mx, v[i]);
    }
    #pragma unroll
    for (int off = 16; off; off >>= 1) mx = fmaxf(mx, __shfl_xor_sync(0xFFFFFFFFu, mx, off));
    if (lane == 0) red[w] = mx;
    __syncthreads();
    float bm = red[0];
    #pragma unroll
    for (int j = 1; j < 8; j++) bm = fmaxf(bm, red[j]);

    float sum = 0.f;
    #pragma unroll
    for (int i = 0; i < 17; i++) sum += expf(v[i] - bm);
    #pragma unroll
    for (int off = 16; off; off >>= 1) sum += __shfl_xor_sync(0xFFFFFFFFu, sum, off);
    __syncthreads();
    if (lane == 0) red[w] = sum;
    __syncthreads();
    if (tid == 0) {
        float tot = 0.f;
        #pragma unroll
        for (int j = 0; j < 8; j++) tot += red[j];
        g_rowm[row] = bm;
        g_rowinv[row] = 1.0f / tot;
    }
}

// ---------------------------------------------------------------------------
// Fused V-cache copy + attn @ V accumulation. Softmax normalization applied
// on the fly while staging probs into smem. Same 2-rows-in-flight pipeline.
// ---------------------------------------------------------------------------
__global__ void __launch_bounds__(256) vcopy_out(const float* __restrict__ vc,
                                                 float* __restrict__ values) {
    int bh = blockIdx.x;
    int start = blockIdx.y * CH2;
    bool last = (blockIdx.y == 7);
    int tid = threadIdx.x, w = tid >> 5, lane = tid & 31;
    __shared__ __align__(16) float sp[(CH2 + 4) * 4];   // [row_local][qi]

    int len = last ? (CH2 + 4) : CH2;
    #pragma unroll
    for (int qi = 0; qi < 4; qi++) {
        float m   = g_rowm[bh * 4 + qi];
        float inv = g_rowinv[bh * 4 + qi];
        for (int i = tid; i < len; i += 256)
            sp[i * 4 + qi] = expf(g_scores[(bh * 4 + qi) * KVT + start + i] - m) * inv;
    }
    __syncthreads();

    const float* vin  = vc     + (bh * KV_ + start) * HD_ + lane * 4;
    float*       vout = values + (bh * KVT + start) * HD_ + lane * 4;

    float a0[4] = {}, a1[4] = {}, a2[4] = {}, a3[4] = {};
    for (int rr = w; rr < CH2; rr += 16) {
        float4 va = *(const float4*)(vin + rr * HD_);
        float4 vb = *(const float4*)(vin + (rr + 8) * HD_);
        *(float4*)(vout + rr * HD_)       = va;
        *(float4*)(vout + (rr + 8) * HD_) = vb;
        float4 pa = *(const float4*)(sp + rr * 4);
        float4 pb = *(const float4*)(sp + (rr + 8) * 4);
        a0[0] += pa.x*va.x; a0[1] += pa.x*va.y; a0[2] += pa.x*va.z; a0[3] += pa.x*va.w;
        a1[0] += pa.y*va.x; a1[1] += pa.y*va.y; a1[2] += pa.y*va.z; a1[3] += pa.y*va.w;
        a2[0] += pa.z*va.x; a2[1] += pa.z*va.y; a2[2] += pa.z*va.z; a2[3] += pa.z*va.w;
        a3[0] += pa.w*va.x; a3[1] += pa.w*va.y; a3[2] += pa.w*va.z; a3[3] += pa.w*va.w;
        a0[0] += pb.x*vb.x; a0[1] += pb.x*vb.y; a0[2] += pb.x*vb.z; a0[3] += pb.x*vb.w;
        a1[0] += pb.y*vb.x; a1[1] += pb.y*vb.y; a1[2] += pb.y*vb.z; a1[3] += pb.y*vb.w;
        a2[0] += pb.z*vb.x; a2[1] += pb.z*vb.y; a2[2] += pb.z*vb.z; a2[3] += pb.z*vb.w;
        a3[0] += pb.w*vb.x; a3[1] += pb.w*vb.y; a3[2] += pb.w*vb.z; a3[3] += pb.w*vb.w;
    }

    if (last && w < 4) {                         // tail rows (already in values)
        int r = KV_ + w;
        float4 v = *(const float4*)(values + (bh * KVT + r) * HD_ + lane * 4);
        float4 p = *(const float4*)(sp + (CH2 + w) * 4);
        a0[0] += p.x*v.x; a0[1] += p.x*v.y; a0[2] += p.x*v.z; a0[3] += p.x*v.w;
        a1[0] += p.y*v.x; a1[1] += p.y*v.y; a1[2] += p.y*v.z; a1[3] += p.y*v.w;
        a2[0] += p.z*v.x; a2[1] += p.z*v.y; a2[2] += p.z*v.z; a2[3] += p.z*v.w;
        a3[0] += p.w*v.x; a3[1] += p.w*v.y; a3[2] += p.w*v.z; a3[3] += p.w*v.w;
    }

    float* ao = g_attnout + bh * 4 * HD_ + lane * 4;
    #pragma unroll
    for (int e = 0; e < 4; e++) {
        atomicAdd(&ao[0 * HD_ + e], a0[e]);
        atomicAdd(&ao[1 * HD_ + e], a1[e]);
        atomicAdd(&ao[2 * HD_ + e], a2[e]);
        atomicAdd(&ao[3 * HD_ + e], a3[e]);
    }
}

// ---------------------------------------------------------------------------
extern "C" void kernel_launch(void* const* d_in, const int* in_sizes, int n_in,
                              void* d_out, int out_size) {
    const float* x    = (const float*)d_in[0];
    const float* mask = (const float*)d_in[1];
    const float* kc   = (const float*)d_in[2];
    const float* vc   = (const float*)d_in[3];
    const float* qw   = (const float*)d_in[4];
    const float* kw   = (const float*)d_in[5];
    const float* vw   = (const float*)d_in[6];
    const float* ow   = (const float*)d_in[7];

    float* out    = (float*)d_out;
    float* keys   = out + OUT_ELEMS;
    float* values = keys + KEYS_ELEMS;

    init_kernel<<<1536, 256>>>(out);

    gemm_qkv<<<dim3(32, SPLITK, 3), 256>>>(x, qw, kw, vw);

    rope_scatter<<<dim3(256, 3), 256>>>(keys, values);

    kcopy_scores<<<dim3(BH, 8), 256>>>(kc, mask, keys);
    rowstat_k<<<BH * L_, 256>>>();
    vcopy_out<<<dim3(BH, 8), 256>>>(vc, values);

    gemm_o<<<dim3(32, 4), 256>>>(ow, out);
}

// round 12
// speedup vs baseline: 1.6412x; 1.0042x over previous
#include <cuda_runtime.h>
#include <math.h>

// Problem constants (fixed shapes)
#define B_    16
#define H_    16
#define BH    256          // B*H
#define L_    4
#define D_    2048
#define HD_   128
#define KV_   4096
#define KVT   4100         // KV + L
#define M_    64           // B*L rows
#define CH2   512          // kv chunk size (8 chunks cover KV exactly)
#define SPLITK 4

// Output layout (concatenated): out[131072], keys[256*4100*128], values[...]
#define OUT_ELEMS   (M_*D_)                 // 131072
#define KEYS_ELEMS  (BH*KVT*HD_)            // 134348800

// Scratch
__device__ float g_qkv[3*M_*D_];            // raw q,k,v projections
__device__ float g_q[BH*L_*HD_];            // roped q, (b,h,l,hd)
__device__ float g_attnout[BH*L_*HD_];      // attention output accum (b,h,l,hd)
__device__ float g_scores[BH*L_*KVT];       // raw scores (pre-softmax)
__device__ float g_rowm[BH*L_];             // per-row max
__device__ float g_rowinv[BH*L_];           // per-row 1/sum(exp)
__device__ float g_rc[L_][64];
__device__ float g_rs[L_][64];

// ---------------------------------------------------------------------------
// init: zero accumulators + out region, build rope table (fp64 trig)
// ---------------------------------------------------------------------------
__global__ void __launch_bounds__(256) init_kernel(float* __restrict__ out) {
    int t = blockIdx.x * blockDim.x + threadIdx.x;
    if (t < 3*M_*D_) g_qkv[t] = 0.f;
    if (t < BH*L_*HD_) { g_attnout[t] = 0.f; out[t] = 0.f; }
    if (t < 256) {
        int l = t >> 6, i = t & 63;
        double inv = pow(10000.0, -(double)(2*i) / 128.0);
        float invf = (float)inv;                       // match jax f32 inv_freq
        float ang = (float)(KV_ + l) * invf;           // f32 angle like reference
        g_rc[l][i] = (float)cos((double)ang);
        g_rs[l][i] = (float)sin((double)ang);
    }
}

// ---------------------------------------------------------------------------
// Fused QKV projection: C[64 x 2048] += A[64 x 2048] * W[2048 x 2048]^T
// blockIdx.z selects q/k/v; blockIdx.y is the split-K slice (atomic combine).
// ---------------------------------------------------------------------------
__global__ void __launch_bounds__(256) gemm_qkv(const float* __restrict__ A,
                         const float* __restrict__ qw,
                         const float* __restrict__ kw,
                         const float* __restrict__ vw) {
    __shared__ float As[32][64];
    __shared__ float Bs[32][64];
    int mode = blockIdx.z;
    const float* __restrict__ W = (mode == 0) ? qw : ((mode == 1) ? kw : vw);
    float* __restrict__ C = g_qkv + mode * M_ * D_;

    int tid = threadIdx.x;
    int tx = tid & 15, ty = tid >> 4;
    int n0 = blockIdx.x * 64;
    int KS = D_ / gridDim.y;
    int kbase = blockIdx.y * KS;

    float acc[4][4] = {};

    for (int k0 = kbase; k0 < kbase + KS; k0 += 32) {
        #pragma unroll
        for (int rep = 0; rep < 2; rep++) {
            int fid = tid + rep * 256;
            int row = fid >> 3;
            int c4  = (fid & 7) * 4;
            int k   = k0 + c4;
            float4 av = *(const float4*)(A + row * D_ + k);
            float4 bv = *(const float4*)(W + (n0 + row) * D_ + k);
            As[c4+0][row] = av.x; As[c4+1][row] = av.y;
            As[c4+2][row] = av.z; As[c4+3][row] = av.w;
            Bs[c4+0][row] = bv.x; Bs[c4+1][row] = bv.y;
            Bs[c4+2][row] = bv.z; Bs[c4+3][row] = bv.w;
        }
        __syncthreads();
        #pragma unroll
        for (int kk = 0; kk < 32; kk++) {
            float a[4], b[4];
            #pragma unroll
            for (int i = 0; i < 4; i++) a[i] = As[kk][ty*4 + i];
            #pragma unroll
            for (int j = 0; j < 4; j++) b[j] = Bs[kk][tx*4 + j];
            #pragma unroll
            for (int i = 0; i < 4; i++)
                #pragma unroll
                for (int j = 0; j < 4; j++)
                    acc[i][j] += a[i] * b[j];
        }
        __syncthreads();
    }

    #pragma unroll
    for (int i = 0; i < 4; i++)
        #pragma unroll
        for (int j = 0; j < 4; j++)
            atomicAdd(&C[(ty*4 + i) * D_ + n0 + tx*4 + j], acc[i][j]);
}

// ---------------------------------------------------------------------------
// O projection: out[64 x 2048] += attnout(gathered) * OW^T, split-K atomic
// ---------------------------------------------------------------------------
__global__ void __launch_bounds__(256) gemm_o(const float* __restrict__ W,
                                              float* __restrict__ C) {
    __shared__ float As[32][64];
    __shared__ float Bs[32][64];
    const float* __restrict__ A = g_attnout;

    int tid = threadIdx.x;
    int tx = tid & 15, ty = tid >> 4;
    int n0 = blockIdx.x * 64;
    int KS = D_ / gridDim.y;
    int kbase = blockIdx.y * KS;

    float acc[4][4] = {};

    for (int k0 = kbase; k0 < kbase + KS; k0 += 32) {
        #pragma unroll
        for (int rep = 0; rep < 2; rep++) {
            int fid = tid + rep * 256;
            int row = fid >> 3;
            int c4  = (fid & 7) * 4;
            int k   = k0 + c4;
            // gather: A row m=(b,l), col k=(h,hd) from (b,h,l,hd) layout
            int b = row >> 2, l = row & 3, h = k >> 7, hd = k & 127;
            float4 av = *(const float4*)(A + (((b << 4) + h) * 4 + l) * HD_ + hd);
            float4 bv = *(const float4*)(W + (n0 + row) * D_ + k);
            As[c4+0][row] = av.x; As[c4+1][row] = av.y;
            As[c4+2][row] = av.z; As[c4+3][row] = av.w;
            Bs[c4+0][row] = bv.x; Bs[c4+1][row] = bv.y;
            Bs[c4+2][row] = bv.z; Bs[c4+3][row] = bv.w;
        }
        __syncthreads();
        #pragma unroll
        for (int kk = 0; kk < 32; kk++) {
            float a[4], b[4];
            #pragma unroll
            for (int i = 0; i < 4; i++) a[i] = As[kk][ty*4 + i];
            #pragma unroll
            for (int j = 0; j < 4; j++) b[j] = Bs[kk][tx*4 + j];
            #pragma unroll
            for (int i = 0; i < 4; i++)
                #pragma unroll
                for (int j = 0; j < 4; j++)
                    acc[i][j] += a[i] * b[j];
        }
        __syncthreads();
    }

    #pragma unroll
    for (int i = 0; i < 4; i++)
        #pragma unroll
        for (int j = 0; j < 4; j++)
            atomicAdd(&C[(ty*4 + i) * D_ + n0 + tx*4 + j], acc[i][j]);
}

// ---------------------------------------------------------------------------
// rope + scatter: q -> g_q (roped), k -> keys tail (roped), v -> values tail
// ---------------------------------------------------------------------------
__global__ void __launch_bounds__(256) rope_scatter(float* __restrict__ keys,
                                                    float* __restrict__ values) {
    int mat = blockIdx.y;                       // 0=q, 1=k, 2=v
    int p = blockIdx.x * 256 + threadIdx.x;     // pair id, 0..65535
    int m  = p >> 10;                            // row 0..63
    int n0 = (p & 1023) * 2;                     // even column
    int b = m >> 2, l = m & 3;
    int h = n0 >> 7, hd = n0 & 127;
    const float* src = g_qkv + mat * M_ * D_ + m * D_ + n0;
    float x1 = src[0], x2 = src[1];
    int bh = (b << 4) + h;
    if (mat == 2) {
        float* dst = values + (bh * KVT + KV_ + l) * HD_ + hd;
        dst[0] = x1; dst[1] = x2;
    } else {
        int i = hd >> 1;
        float c = g_rc[l][i], s = g_rs[l][i];
        float r1 = x1 * c - x2 * s;
        float r2 = x1 * s + x2 * c;
        if (mat == 0) {
            float* dst = g_q + (bh * 4 + l) * HD_ + hd;
            dst[0] = r1; dst[1] = r2;
        } else {
            float* dst = keys + (bh * KVT + KV_ + l) * HD_ + hd;
            dst[0] = r1; dst[1] = r2;
        }
    }
}

// ---------------------------------------------------------------------------
// helpers for the streaming kernels
// ---------------------------------------------------------------------------
__device__ __forceinline__ void dot4(float4 kv, float4 q0, float4 q1,
                                     float4 q2, float4 q3,
                                     float& s0, float& s1, float& s2, float& s3) {
    s0 = kv.x*q0.x + kv.y*q0.y + kv.z*q0.z + kv.w*q0.w;
    s1 = kv.x*q1.x + kv.y*q1.y + kv.z*q1.z + kv.w*q1.w;
    s2 = kv.x*q2.x + kv.y*q2.y + kv.z*q2.z + kv.w*q2.w;
    s3 = kv.x*q3.x + kv.y*q3.y + kv.z*q3.z + kv.w*q3.w;
}

__device__ __forceinline__ void red4(float& s0, float& s1, float& s2, float& s3) {
    #pragma unroll
    for (int off = 16; off; off >>= 1) {
        s0 += __shfl_xor_sync(0xFFFFFFFFu, s0, off);
        s1 += __shfl_xor_sync(0xFFFFFFFFu, s1, off);
        s2 += __shfl_xor_sync(0xFFFFFFFFu, s2, off);
        s3 += __shfl_xor_sync(0xFFFFFFFFu, s3, off);
    }
}

__device__ __forceinline__ float4 ldcs4(const float* p) {
    return __ldcs((const float4*)p);
}
__device__ __forceinline__ void stcs4(float* p, float4 v) {
    __stcs((float4*)p, v);
}

// ---------------------------------------------------------------------------
// Fused K-cache copy + scores: warp per kv row, 4 rows in flight per warp,
// streaming cache hints (read-once / write-once), tail rows in chunk 7.
// ---------------------------------------------------------------------------
__global__ void __launch_bounds__(256, 3) kcopy_scores(
        const float* __restrict__ kc, const float* __restrict__ mask,
        float* __restrict__ keys) {
    int bh = blockIdx.x;
    int start = blockIdx.y * CH2;               // 0..3584, chunks cover [0,4096)
    bool last = (blockIdx.y == 7);
    int tid = threadIdx.x, w = tid >> 5, lane = tid & 31;
    __shared__ float ssc[4][CH2 + 4];

    const float* qb = g_q + bh * 4 * HD_ + lane * 4;
    float4 q0 = *(const float4*)(qb + 0 * HD_);
    float4 q1 = *(const float4*)(qb + 1 * HD_);
    float4 q2 = *(const float4*)(qb + 2 * HD_);
    float4 q3 = *(const float4*)(qb + 3 * HD_);

    const float* kin  = kc   + (bh * KV_ + start) * HD_ + lane * 4;
    float*       kout = keys + (bh * KVT + start) * HD_ + lane * 4;

    for (int rr = w; rr < CH2; rr += 32) {
        // issue all four loads before any dependent work (MLP=4 per warp)
        float4 ka = ldcs4(kin + (rr      ) * HD_);
        float4 kb = ldcs4(kin + (rr +  8) * HD_);
        float4 kd = ldcs4(kin + (rr + 16) * HD_);
        float4 ke = ldcs4(kin + (rr + 24) * HD_);
        stcs4(kout + (rr      ) * HD_, ka);
        stcs4(kout + (rr +  8) * HD_, kb);
        stcs4(kout + (rr + 16) * HD_, kd);
        stcs4(kout + (rr + 24) * HD_, ke);
        float a0, a1, a2, a3, b0, b1, b2, b3;
        float d0, d1, d2, d3, e0, e1, e2, e3;
        dot4(ka, q0, q1, q2, q3, a0, a1, a2, a3);
        dot4(kb, q0, q1, q2, q3, b0, b1, b2, b3);
        dot4(kd, q0, q1, q2, q3, d0, d1, d2, d3);
        dot4(ke, q0, q1, q2, q3, e0, e1, e2, e3);
        red4(a0, a1, a2, a3);
        red4(b0, b1, b2, b3);
        red4(d0, d1, d2, d3);
        red4(e0, e1, e2, e3);
        if (lane == 0) {
            ssc[0][rr     ] = a0; ssc[1][rr     ] = a1; ssc[2][rr     ] = a2; ssc[3][rr     ] = a3;
            ssc[0][rr +  8] = b0; ssc[1][rr +  8] = b1; ssc[2][rr +  8] = b2; ssc[3][rr +  8] = b3;
            ssc[0][rr + 16] = d0; ssc[1][rr + 16] = d1; ssc[2][rr + 16] = d2; ssc[3][rr + 16] = d3;
            ssc[0][rr + 24] = e0; ssc[1][rr + 24] = e1; ssc[2][rr + 24] = e2; ssc[3][rr + 24] = e3;
        }
    }

    if (last && w < 4) {                         // tail rows 4096..4099 (already in keys)
        int r = KV_ + w;
        float4 kv = *(const float4*)(keys + (bh * KVT + r) * HD_ + lane * 4);
        float t0, t1, t2, t3;
        dot4(kv, q0, q1, q2, q3, t0, t1, t2, t3);
        red4(t0, t1, t2, t3);
        if (lane == 0) {
            ssc[0][CH2 + w] = t0; ssc[1][CH2 + w] = t1;
            ssc[2][CH2 + w] = t2; ssc[3][CH2 + w] = t3;
        }
    }
    __syncthreads();

    const float scale = 0.08838834764831845f;   // 128^-0.5
    int len = last ? (CH2 + 4) : CH2;
    #pragma unroll
    for (int qi = 0; qi < 4; qi++)
        for (int i = tid; i < len; i += 256)
            g_scores[(bh * 4 + qi) * KVT + start + i] =
                ssc[qi][i] * scale + mask[qi * KVT + start + i];
}

// ---------------------------------------------------------------------------
// Row stats: per-row max and 1/sum(exp) over 4100 elems (register-resident)
// ---------------------------------------------------------------------------
__global__ void __launch_bounds__(256) rowstat_k() {
    int row = blockIdx.x;                  // bh*4+qi, 0..1023
    const float* s = g_scores + row * KVT;
    int tid = threadIdx.x, lane = tid & 31, w = tid >> 5;
    __shared__ float red[8];

    float v[17];
    float mx = -3.0e38f;
    #pragma unroll
    for (int i = 0; i < 17; i++) {
        int idx = tid + i * 256;
        v[i] = (idx < KVT) ? s[idx] : -3.0e38f;
        mx = fmaxf(mx, v[i]);
    }
    #pragma unroll
    for (int off = 16; off; off >>= 1) mx = fmaxf(mx, __shfl_xor_sync(0xFFFFFFFFu, mx, off));
    if (lane == 0) red[w] = mx;
    __syncthreads();
    float bm = red[0];
    #pragma unroll
    for (int j = 1; j < 8; j++) bm = fmaxf(bm, red[j]);

    float sum = 0.f;
    #pragma unroll
    for (int i = 0; i < 17; i++) sum += expf(v[i] - bm);
    #pragma unroll
    for (int off = 16; off; off >>= 1) sum += __shfl_xor_sync(0xFFFFFFFFu, sum, off);
    __syncthreads();
    if (lane == 0) red[w] = sum;
    __syncthreads();
    if (tid == 0) {
        float tot = 0.f;
        #pragma unroll
        for (int j = 0; j < 8; j++) tot += red[j];
        g_rowm[row] = bm;
        g_rowinv[row] = 1.0f / tot;
    }
}

// ---------------------------------------------------------------------------
// Fused V-cache copy + attn @ V accumulation. Softmax normalization applied
// on the fly while staging probs into smem. 4 rows in flight per warp.
// ---------------------------------------------------------------------------
__global__ void __launch_bounds__(256, 3) vcopy_out(const float* __restrict__ vc,
                                                    float* __restrict__ values) {
    int bh = blockIdx.x;
    int start = blockIdx.y * CH2;
    bool last = (blockIdx.y == 7);
    int tid = threadIdx.x, w = tid >> 5, lane = tid & 31;
    __shared__ __align__(16) float sp[(CH2 + 4) * 4];   // [row_local][qi]

    int len = last ? (CH2 + 4) : CH2;
    #pragma unroll
    for (int qi = 0; qi < 4; qi++) {
        float m   = g_rowm[bh * 4 + qi];
        float inv = g_rowinv[bh * 4 + qi];
        for (int i = tid; i < len; i += 256)
            sp[i * 4 + qi] = expf(g_scores[(bh * 4 + qi) * KVT + start + i] - m) * inv;
    }
    __syncthreads();

    const float* vin  = vc     + (bh * KV_ + start) * HD_ + lane * 4;
    float*       vout = values + (bh * KVT + start) * HD_ + lane * 4;

    float a0[4] = {}, a1[4] = {}, a2[4] = {}, a3[4] = {};
    for (int rr = w; rr < CH2; rr += 32) {
        float4 va = ldcs4(vin + (rr      ) * HD_);
        float4 vb = ldcs4(vin + (rr +  8) * HD_);
        float4 vd = ldcs4(vin + (rr + 16) * HD_);
        float4 ve = ldcs4(vin + (rr + 24) * HD_);
        stcs4(vout + (rr      ) * HD_, va);
        stcs4(vout + (rr +  8) * HD_, vb);
        stcs4(vout + (rr + 16) * HD_, vd);
        stcs4(vout + (rr + 24) * HD_, ve);
        float4 pa = *(const float4*)(sp + (rr      ) * 4);
        float4 pb = *(const float4*)(sp + (rr +  8) * 4);
        float4 pd = *(const float4*)(sp + (rr + 16) * 4);
        float4 pe = *(const float4*)(sp + (rr + 24) * 4);
        a0[0] += pa.x*va.x; a0[1] += pa.x*va.y; a0[2] += pa.x*va.z; a0[3] += pa.x*va.w;
        a1[0] += pa.y*va.x; a1[1] += pa.y*va.y; a1[2] += pa.y*va.z; a1[3] += pa.y*va.w;
        a2[0] += pa.z*va.x; a2[1] += pa.z*va.y; a2[2] += pa.z*va.z; a2[3] += pa.z*va.w;
        a3[0] += pa.w*va.x; a3[1] += pa.w*va.y; a3[2] += pa.w*va.z; a3[3] += pa.w*va.w;
        a0[0] += pb.x*vb.x; a0[1] += pb.x*vb.y; a0[2] += pb.x*vb.z; a0[3] += pb.x*vb.w;
        a1[0] += pb.y*vb.x; a1[1] += pb.y*vb.y; a1[2] += pb.y*vb.z; a1[3] += pb.y*vb.w;
        a2[0] += pb.z*vb.x; a2[1] += pb.z*vb.y; a2[2] += pb.z*vb.z; a2[3] += pb.z*vb.w;
        a3[0] += pb.w*vb.x; a3[1] += pb.w*vb.y; a3[2] += pb.w*vb.z; a3[3] += pb.w*vb.w;
        a0[0] += pd.x*vd.x; a0[1] += pd.x*vd.y; a0[2] += pd.x*vd.z; a0[3] += pd.x*vd.w;
        a1[0] += pd.y*vd.x; a1[1] += pd.y*vd.y; a1[2] += pd.y*vd.z; a1[3] += pd.y*vd.w;
        a2[0] += pd.z*vd.x; a2[1] += pd.z*vd.y; a2[2] += pd.z*vd.z; a2[3] += pd.z*vd.w;
        a3[0] += pd.w*vd.x; a3[1] += pd.w*vd.y; a3[2] += pd.w*vd.z; a3[3] += pd.w*vd.w;
        a0[0] += pe.x*ve.x; a0[1] += pe.x*ve.y; a0[2] += pe.x*ve.z; a0[3] += pe.x*ve.w;
        a1[0] += pe.y*ve.x; a1[1] += pe.y*ve.y; a1[2] += pe.y*ve.z; a1[3] += pe.y*ve.w;
        a2[0] += pe.z*ve.x; a2[1] += pe.z*ve.y; a2[2] += pe.z*ve.z; a2[3] += pe.z*ve.w;
        a3[0] += pe.w*ve.x; a3[1] += pe.w*ve.y; a3[2] += pe.w*ve.z; a3[3] += pe.w*ve.w;
    }

    if (last && w < 4) {                         // tail rows (already in values)
        int r = KV_ + w;
        float4 v = *(const float4*)(values + (bh * KVT + r) * HD_ + lane * 4);
        float4 p = *(const float4*)(sp + (CH2 + w) * 4);
        a0[0] += p.x*v.x; a0[1] += p.x*v.y; a0[2] += p.x*v.z; a0[3] += p.x*v.w;
        a1[0] += p.y*v.x; a1[1] += p.y*v.y; a1[2] += p.y*v.z; a1[3] += p.y*v.w;
        a2[0] += p.z*v.x; a2[1] += p.z*v.y; a2[2] += p.z*v.z; a2[3] += p.z*v.w;
        a3[0] += p.w*v.x; a3[1] += p.w*v.y; a3[2] += p.w*v.z; a3[3] += p.w*v.w;
    }

    float* ao = g_attnout + bh * 4 * HD_ + lane * 4;
    #pragma unroll
    for (int e = 0; e < 4; e++) {
        atomicAdd(&ao[0 * HD_ + e], a0[e]);
        atomicAdd(&ao[1 * HD_ + e], a1[e]);
        atomicAdd(&ao[2 * HD_ + e], a2[e]);
        atomicAdd(&ao[3 * HD_ + e], a3[e]);
    }
}

// ---------------------------------------------------------------------------
extern "C" void kernel_launch(void* const* d_in, const int* in_sizes, int n_in,
                              void* d_out, int out_size) {
    const float* x    = (const float*)d_in[0];
    const float* mask = (const float*)d_in[1];
    const float* kc   = (const float*)d_in[2];
    const float* vc   = (const float*)d_in[3];
    const float* qw   = (const float*)d_in[4];
    const float* kw   = (const float*)d_in[5];
    const float* vw   = (const float*)d_in[6];
    const float* ow   = (const float*)d_in[7];

    float* out    = (float*)d_out;
    float* keys   = out + OUT_ELEMS;
    float* values = keys + KEYS_ELEMS;

    init_kernel<<<1536, 256>>>(out);

    gemm_qkv<<<dim3(32, SPLITK, 3), 256>>>(x, qw, kw, vw);

    rope_scatter<<<dim3(256, 3), 256>>>(keys, values);

    kcopy_scores<<<dim3(BH, 8), 256>>>(kc, mask, keys);
    rowstat_k<<<BH * L_, 256>>>();
    vcopy_out<<<dim3(BH, 8), 256>>>(vc, values);

    gemm_o<<<dim3(32, 4), 256>>>(ow, out);
}